// round 7
// baseline (speedup 1.0000x reference)
#include <cuda_runtime.h>
#include <cuda_fp16.h>
#include <math.h>
#include <stdint.h>

#define B_  16
#define C_  768
#define N_  4096
#define BN_ 65536
#define M_  1024

#define KC      64                    // K halves per pipeline chunk (4 x k16 mma)
#define STAGES  3
#define A_BYTES (128 * 128)           // 128 rows x 64 halves (swizzled)
#define B_BYTES (256 * 128)           // 256 rows x 64 halves
#define DYN_SMEM (STAGES * (A_BYTES + B_BYTES))   // 147456 B, 1 CTA/SM

// scratch (allocation-free __device__ globals)
__device__ __half g_zh[(size_t)BN_ * C_];     // half(z * rz), K-major [bn][c]
__device__ __half g_memh[M_ * C_];            // half(mem * rm)        [m][c]
__device__ __half g_memTh[C_ * M_];           // half(mem) transposed  [c][m]
__device__ __half g_attnh[(size_t)BN_ * M_];  // half(attn)            [bn][m]
__device__ float  g_rm[M_];

// ---------------------------------------------------------------- helpers ---
__device__ __forceinline__ uint32_t smem_u32(const void* p) {
    uint32_t a;
    asm("{ .reg .u64 t; cvta.to.shared.u64 t, %1; cvt.u32.u64 %0, t; }"
        : "=r"(a) : "l"(p));
    return a;
}
__device__ __forceinline__ void cp16(uint32_t dst, const void* src) {
    asm volatile("cp.async.cg.shared.global [%0], [%1], 16;" :: "r"(dst), "l"(src));
}
__device__ __forceinline__ void cp_commit() {
    asm volatile("cp.async.commit_group;\n" ::: "memory");
}
template <int W>
__device__ __forceinline__ void cp_wait() {
    asm volatile("cp.async.wait_group %0;\n" :: "n"(W) : "memory");
}
__device__ __forceinline__ void mma16(float* d, const uint32_t* a, const uint32_t* b) {
    asm volatile(
        "mma.sync.aligned.m16n8k16.row.col.f32.f16.f16.f32 "
        "{%0,%1,%2,%3}, {%4,%5,%6,%7}, {%8,%9}, {%0,%1,%2,%3};\n"
        : "+f"(d[0]), "+f"(d[1]), "+f"(d[2]), "+f"(d[3])
        : "r"(a[0]), "r"(a[1]), "r"(a[2]), "r"(a[3]), "r"(b[0]), "r"(b[1]));
}
__device__ __forceinline__ void ldm_x4(uint32_t* r, uint32_t addr) {
    asm volatile("ldmatrix.sync.aligned.m8n8.x4.shared.b16 {%0,%1,%2,%3}, [%4];"
                 : "=r"(r[0]), "=r"(r[1]), "=r"(r[2]), "=r"(r[3]) : "r"(addr));
}
// swizzled physical byte offset: row r (stride 128B), 16B chunk c -> c ^ (r&7)
__device__ __forceinline__ uint32_t swz(int r, int c) {
    return (uint32_t)(r * 128) + (uint32_t)((c ^ (r & 7)) << 4);
}

// stage loader: A 128 rows, B 256 rows, KC halves each, 16B per cp.async
__device__ __forceinline__ void load_tile(uint32_t dstA, uint32_t dstB,
                                          const __half* srcA, const __half* srcB,
                                          int tid, int ldA, int ldB) {
#pragma unroll
    for (int q = 0; q < 4; ++q) {
        int e = q * 256 + tid;
        int r = e >> 3, kq = e & 7;
        cp16(dstA + swz(r, kq), srcA + (size_t)r * ldA + kq * 8);
    }
#pragma unroll
    for (int q = 0; q < 8; ++q) {
        int e = q * 256 + tid;
        int r = e >> 3, kq = e & 7;
        cp16(dstB + swz(r, kq), srcB + (size_t)r * ldB + kq * 8);
    }
}

// ------------------------------------------------------------- GEMM core ----
// D[128 x 256] = A[128 x K] * B[256 x K]^T, fp16 in, fp32 acc.
// 8 warps as 2x4; warp tile 64x64; 3-stage cp.async pipeline; ldmatrix frags.
__device__ __forceinline__ void gemm_main(char* sm_, int T_,
                                          const __half* Asrc, const __half* Bsrc,
                                          int ldA, int ldB, int tid,
                                          int wm, int wn, int lane,
                                          float acc[4][8][4]) {
#pragma unroll
    for (int i = 0; i < 4; ++i)
#pragma unroll
        for (int j = 0; j < 8; ++j)
#pragma unroll
            for (int q = 0; q < 4; ++q) acc[i][j][q] = 0.f;

    uint32_t Asm = smem_u32(sm_);
    uint32_t Bsm = Asm + STAGES * A_BYTES;

    const int l7 = lane & 7, lg = lane >> 3;          // lg: 0..3
    int rowA[4], rowB[4];
#pragma unroll
    for (int mt = 0; mt < 4; ++mt) rowA[mt] = wm * 64 + mt * 16 + (lg & 1) * 8 + l7;
#pragma unroll
    for (int p = 0; p < 4; ++p)    rowB[p] = wn * 64 + p * 16 + (lg >> 1) * 8 + l7;
    const int cA = lg >> 1;                            // A chunk offset
    const int cB = lg & 1;                             // B chunk offset

    load_tile(Asm, Bsm, Asrc, Bsrc, tid, ldA, ldB);
    cp_commit();
    load_tile(Asm + A_BYTES, Bsm + B_BYTES, Asrc + KC, Bsrc + KC, tid, ldA, ldB);
    cp_commit();

    for (int it = 0; it < T_; ++it) {
        cp_wait<1>();
        __syncthreads();   // data visible to all warps; also guards stage reuse
        if (it + 2 < T_) {
            int s = (it + 2) % STAGES;
            load_tile(Asm + s * A_BYTES, Bsm + s * B_BYTES,
                      Asrc + (size_t)(it + 2) * KC, Bsrc + (size_t)(it + 2) * KC,
                      tid, ldA, ldB);
        }
        cp_commit();
        uint32_t Ab = Asm + (it % STAGES) * A_BYTES;
        uint32_t Bb = Bsm + (it % STAGES) * B_BYTES;
#pragma unroll
        for (int kk = 0; kk < KC; kk += 16) {
            const int ck = kk >> 3;
            uint32_t af[4][4], bf[8][2];
#pragma unroll
            for (int mt = 0; mt < 4; ++mt)
                ldm_x4(af[mt], Ab + swz(rowA[mt], ck + cA));
#pragma unroll
            for (int p = 0; p < 4; ++p) {
                uint32_t t[4];
                ldm_x4(t, Bb + swz(rowB[p], ck + cB));
                bf[2 * p][0] = t[0];
                bf[2 * p][1] = t[1];
                bf[2 * p + 1][0] = t[2];
                bf[2 * p + 1][1] = t[3];
            }
#pragma unroll
            for (int mt = 0; mt < 4; ++mt)
#pragma unroll
                for (int nt = 0; nt < 8; ++nt) mma16(acc[mt][nt], af[mt], bf[nt]);
        }
        // no trailing sync: next iter's top sync precedes any overwrite of
        // the stage read here (3-stage rotation).
    }
}

// ---------------------------------------------------------------- prep ------
__global__ void k_rnorm_m(const float* __restrict__ mem) {
    int m = blockIdx.x;
    const float* p = mem + m * C_;
    float acc = 0.f;
    for (int c = threadIdx.x; c < C_; c += 128) {
        float v = p[c];
        acc = fmaf(v, v, acc);
    }
#pragma unroll
    for (int o = 16; o; o >>= 1) acc += __shfl_xor_sync(0xffffffffu, acc, o);
    __shared__ float s[4];
    if ((threadIdx.x & 31) == 0) s[threadIdx.x >> 5] = acc;
    __syncthreads();
    if (threadIdx.x == 0)
        g_rm[m] = 1.0f / fmaxf(sqrtf(s[0] + s[1] + s[2] + s[3]), 1e-12f);
}

__global__ void k_prep(const float* __restrict__ mem) {
    __shared__ float t[32][33];
    int c0 = blockIdx.x << 5, m0 = blockIdx.y << 5;
    int tx = threadIdx.x, ty = threadIdx.y;
    float v = mem[(size_t)(m0 + ty) * C_ + c0 + tx];
    g_memh[(size_t)(m0 + ty) * C_ + c0 + tx] = __float2half_rn(v * g_rm[m0 + ty]);
    t[ty][tx] = v;
    __syncthreads();
    g_memTh[(size_t)(c0 + ty) * M_ + m0 + tx] = __float2half_rn(t[tx][ty]);
}

// zh[bn][c] = half(z[b,c,n] * rz[bn])  — fused transpose + L2 norm
__global__ void __launch_bounds__(256) k_zt_h(const float* __restrict__ z) {
    extern __shared__ float tile[];   // [768][33]
    __shared__ float part[8][32];
    __shared__ float rzv[32];
    int blk = blockIdx.x;
    int b = blk >> 7;
    int n0 = (blk & 127) << 5;
    const float* zb = z + (size_t)b * (C_ * N_) + n0;
    int tid = threadIdx.x;
    for (int e = tid; e < C_ * 32; e += 256) {
        int c = e >> 5, nl = e & 31;
        tile[c * 33 + nl] = zb[(size_t)c * N_ + nl];
    }
    __syncthreads();
    {
        int col = tid & 31, j = tid >> 5;
        float acc = 0.f;
        for (int c = j; c < C_; c += 8) {
            float v = tile[c * 33 + col];
            acc = fmaf(v, v, acc);
        }
        part[j][col] = acc;
    }
    __syncthreads();
    if (tid < 32) {
        float s = 0.f;
#pragma unroll
        for (int j = 0; j < 8; ++j) s += part[j][tid];
        rzv[tid] = 1.0f / fmaxf(sqrtf(s), 1e-12f);
    }
    __syncthreads();
    __half* out = g_zh + (size_t)(b * N_ + n0) * C_;
    for (int e = tid; e < C_ * 32; e += 256) {
        int nl = e / C_;
        int c = e - nl * C_;
        out[(size_t)nl * C_ + c] = __float2half_rn(tile[c * 33 + nl] * rzv[nl]);
    }
}

// ---------------------------------------------------------------- GEMM1 -----
// scores[row][m0+0..255] = sum_c zh[row][c] * memh[m][c]
__global__ void __launch_bounds__(256, 1) k_gemm1_h(float* __restrict__ scores) {
    extern __shared__ __align__(128) char sm_[];
    const int tid = threadIdx.x, lane = tid & 31, warp = tid >> 5;
    const int g = lane >> 2, tg = lane & 3;
    const int wm = warp >> 2, wn = warp & 3;
    const int m0 = blockIdx.x * 256;
    const int row0 = blockIdx.y * 128;

    float acc[4][8][4];
    gemm_main(sm_, C_ / KC, g_zh + (size_t)row0 * C_, g_memh + (size_t)m0 * C_,
              C_, C_, tid, wm, wn, lane, acc);

#pragma unroll
    for (int mt = 0; mt < 4; ++mt) {
        int r = row0 + wm * 64 + mt * 16 + g;
#pragma unroll
        for (int nt = 0; nt < 8; ++nt) {
            int col = m0 + wn * 64 + nt * 8 + 2 * tg;
            float2 o;
            o.x = acc[mt][nt][0];
            o.y = acc[mt][nt][1];
            *(float2*)(scores + (size_t)r * M_ + col) = o;
            o.x = acc[mt][nt][2];
            o.y = acc[mt][nt][3];
            *(float2*)(scores + (size_t)(r + 8) * M_ + col) = o;
        }
    }
}

// ---------------------------------------------------------------- GEMM2 -----
// zhat[b, c0+0..255, n0+0..127] = sum_m attnh[row][m] * memTh[c][m]
// Epilogue transposes through smem for fully-coalesced writes along n.
__global__ void __launch_bounds__(256, 1) k_gemm2_h(float* __restrict__ zhat) {
    extern __shared__ __align__(128) char sm_[];
    const int tid = threadIdx.x, lane = tid & 31, warp = tid >> 5;
    const int g = lane >> 2, tg = lane & 3;
    const int wm = warp >> 2, wn = warp & 3;
    const int c0 = blockIdx.x * 256;
    const int row0 = blockIdx.y * 128;

    float acc[4][8][4];
    gemm_main(sm_, M_ / KC, g_attnh + (size_t)row0 * M_, g_memTh + (size_t)c0 * M_,
              M_, M_, tid, wm, wn, lane, acc);

    __syncthreads();   // all smem reads of the mainloop done; reuse as staging
    float* smf = (float*)sm_;          // [256 cols][132] (stride pad, 135168 B)
#pragma unroll
    for (int mt = 0; mt < 4; ++mt) {
        int r = wm * 64 + mt * 16 + g;
#pragma unroll
        for (int nt = 0; nt < 8; ++nt) {
            int col = wn * 64 + nt * 8 + 2 * tg;
            smf[(size_t)col * 132 + r]           = acc[mt][nt][0];
            smf[(size_t)(col + 1) * 132 + r]     = acc[mt][nt][1];
            smf[(size_t)col * 132 + r + 8]       = acc[mt][nt][2];
            smf[(size_t)(col + 1) * 132 + r + 8] = acc[mt][nt][3];
        }
    }
    __syncthreads();

    const int b = row0 >> 12;
    const int n0 = row0 & (N_ - 1);
    float* base = zhat + (size_t)b * (C_ * N_) + n0;
    // 256 cols x 128 floats; each row = 32 float4, written coalesced
#pragma unroll
    for (int p = 0; p < 32; ++p) {
        int e = p * 256 + tid;
        int cc = e >> 5, q4 = e & 31;
        float4 v = *(const float4*)(smf + (size_t)cc * 132 + q4 * 4);
        *(float4*)(base + (size_t)(c0 + cc) * N_ + q4 * 4) = v;
    }
}

// ---------------------------------------------------------------- softmax ---
// float attn (exact output to d_out) + half copy for GEMM2
__global__ void k_softmax(float* __restrict__ attn) {
    const size_t row = blockIdx.x;
    float* p = attn + row * M_;
    const int t = threadIdx.x;
    float v[8];
    *(float4*)(v)     = *(const float4*)(p + t * 8);
    *(float4*)(v + 4) = *(const float4*)(p + t * 8 + 4);
    float mx = v[0];
#pragma unroll
    for (int i = 1; i < 8; ++i) mx = fmaxf(mx, v[i]);
#pragma unroll
    for (int o = 16; o; o >>= 1) mx = fmaxf(mx, __shfl_xor_sync(0xffffffffu, mx, o));
    __shared__ float red[4];
    if ((t & 31) == 0) red[t >> 5] = mx;
    __syncthreads();
    mx = fmaxf(fmaxf(red[0], red[1]), fmaxf(red[2], red[3]));
    __syncthreads();
    float sum = 0.f;
#pragma unroll
    for (int i = 0; i < 8; ++i) {
        v[i] = expf(v[i] - mx);
        sum += v[i];
    }
#pragma unroll
    for (int o = 16; o; o >>= 1) sum += __shfl_xor_sync(0xffffffffu, sum, o);
    if ((t & 31) == 0) red[t >> 5] = sum;
    __syncthreads();
    sum = red[0] + red[1] + red[2] + red[3];
    float r = 1.0f / sum;
#pragma unroll
    for (int i = 0; i < 8; ++i) v[i] *= r;
    *(float4*)(p + t * 8)     = *(const float4*)(v);
    *(float4*)(p + t * 8 + 4) = *(const float4*)(v + 4);
    __half2 h0 = __floats2half2_rn(v[0], v[1]);
    __half2 h1 = __floats2half2_rn(v[2], v[3]);
    __half2 h2 = __floats2half2_rn(v[4], v[5]);
    __half2 h3 = __floats2half2_rn(v[6], v[7]);
    uint4 u;
    u.x = *(uint32_t*)&h0;
    u.y = *(uint32_t*)&h1;
    u.z = *(uint32_t*)&h2;
    u.w = *(uint32_t*)&h3;
    *(uint4*)(g_attnh + row * M_ + t * 8) = u;
}

// ---------------------------------------------------------------------------
extern "C" void kernel_launch(void* const* d_in, const int* in_sizes, int n_in,
                              void* d_out, int out_size) {
    const float* z   = (const float*)d_in[0];
    const float* mem = (const float*)d_in[1];
    float* zhat = (float*)d_out;
    float* attn = zhat + (size_t)B_ * C_ * N_;

    cudaFuncSetAttribute(k_zt_h, cudaFuncAttributeMaxDynamicSharedMemorySize, C_ * 33 * 4);
    cudaFuncSetAttribute(k_gemm1_h, cudaFuncAttributeMaxDynamicSharedMemorySize, DYN_SMEM);
    cudaFuncSetAttribute(k_gemm2_h, cudaFuncAttributeMaxDynamicSharedMemorySize, DYN_SMEM);

    k_rnorm_m<<<M_, 128>>>(mem);
    k_prep<<<dim3(C_ / 32, M_ / 32), dim3(32, 32)>>>(mem);
    k_zt_h<<<BN_ / 32, 256, C_ * 33 * 4>>>(z);
    k_gemm1_h<<<dim3(M_ / 256, BN_ / 128), 256, DYN_SMEM>>>(attn);
    k_softmax<<<BN_, 128>>>(attn);
    k_gemm2_h<<<dim3(C_ / 256, BN_ / 128), 256, DYN_SMEM>>>(zhat);
}

// round 8
// speedup vs baseline: 1.0927x; 1.0927x over previous
#include <cuda_runtime.h>
#include <cuda_fp16.h>
#include <math.h>
#include <stdint.h>

#define B_  16
#define C_  768
#define N_  4096
#define BN_ 65536
#define M_  1024

#define KC      64                   // K halves per pipeline chunk (4 x k16 mma)
#define STAGES  3
#define STAGE_BYTES (128 * 128)      // 128 rows x 64 halves, swizzled, no pad
#define DYN_SMEM (STAGES * 2 * STAGE_BYTES)   // 98304 B -> 2 CTAs/SM

// scratch (allocation-free __device__ globals)
__device__ __half g_zh[(size_t)BN_ * C_];     // half(z * rz), K-major [bn][c]
__device__ __half g_memh[M_ * C_];            // half(mem * rm)        [m][c]
__device__ __half g_memTh[C_ * M_];           // half(mem) transposed  [c][m]
__device__ __half g_attnh[(size_t)BN_ * M_];  // half(attn)            [bn][m]
__device__ float  g_rm[M_];

// ---------------------------------------------------------------- helpers ---
__device__ __forceinline__ uint32_t smem_u32(const void* p) {
    uint32_t a;
    asm("{ .reg .u64 t; cvta.to.shared.u64 t, %1; cvt.u32.u64 %0, t; }"
        : "=r"(a) : "l"(p));
    return a;
}
__device__ __forceinline__ void cp16(uint32_t dst, const void* src) {
    asm volatile("cp.async.cg.shared.global [%0], [%1], 16;" :: "r"(dst), "l"(src));
}
__device__ __forceinline__ void cp_commit() {
    asm volatile("cp.async.commit_group;\n" ::: "memory");
}
template <int W>
__device__ __forceinline__ void cp_wait() {
    asm volatile("cp.async.wait_group %0;\n" :: "n"(W) : "memory");
}
__device__ __forceinline__ void mma16(float* d, const uint32_t* a, const uint32_t* b) {
    asm volatile(
        "mma.sync.aligned.m16n8k16.row.col.f32.f16.f16.f32 "
        "{%0,%1,%2,%3}, {%4,%5,%6,%7}, {%8,%9}, {%0,%1,%2,%3};\n"
        : "+f"(d[0]), "+f"(d[1]), "+f"(d[2]), "+f"(d[3])
        : "r"(a[0]), "r"(a[1]), "r"(a[2]), "r"(a[3]), "r"(b[0]), "r"(b[1]));
}
__device__ __forceinline__ void ldm_x4(uint32_t* r, uint32_t addr) {
    asm volatile("ldmatrix.sync.aligned.m8n8.x4.shared.b16 {%0,%1,%2,%3}, [%4];"
                 : "=r"(r[0]), "=r"(r[1]), "=r"(r[2]), "=r"(r[3]) : "r"(addr));
}
// swizzled physical byte offset: row r (stride 128B), 16B chunk c -> c ^ (r&7)
__device__ __forceinline__ uint32_t swz(int r, int c) {
    return (uint32_t)(r * 128) + (uint32_t)((c ^ (r & 7)) << 4);
}

// stage loader: 128 rows x KC halves each for A and B, 16B per cp.async
__device__ __forceinline__ void load_tile(uint32_t dstA, uint32_t dstB,
                                          const __half* srcA, const __half* srcB,
                                          int tid, int ldA, int ldB) {
#pragma unroll
    for (int q = 0; q < 4; ++q) {
        int e = q * 256 + tid;
        int r = e >> 3, kq = e & 7;
        cp16(dstA + swz(r, kq), srcA + (size_t)r * ldA + kq * 8);
    }
#pragma unroll
    for (int q = 0; q < 4; ++q) {
        int e = q * 256 + tid;
        int r = e >> 3, kq = e & 7;
        cp16(dstB + swz(r, kq), srcB + (size_t)r * ldB + kq * 8);
    }
}

// ------------------------------------------------------------- GEMM core ----
// D[128 x 128] = A[128 x K] * B[128 x K]^T, fp16 in, fp32 acc.
// 8 warps as 2x4; warp tile 64x32; 3-stage cp.async pipeline; ldmatrix frags;
// single barrier per iteration (trailing barrier proven redundant w/ 3 stages).
__device__ __forceinline__ void gemm_main(char* sm_, int T_,
                                          const __half* Asrc, const __half* Bsrc,
                                          int ldA, int ldB, int tid,
                                          int wm, int wn, int lane,
                                          float acc[4][4][4]) {
#pragma unroll
    for (int i = 0; i < 4; ++i)
#pragma unroll
        for (int j = 0; j < 4; ++j)
#pragma unroll
            for (int q = 0; q < 4; ++q) acc[i][j][q] = 0.f;

    uint32_t Asm = smem_u32(sm_);
    uint32_t Bsm = Asm + STAGES * STAGE_BYTES;

    const int l7 = lane & 7, lg = lane >> 3;          // lg: 0..3
    int rowA[4], rowB[2];
#pragma unroll
    for (int mt = 0; mt < 4; ++mt) rowA[mt] = wm * 64 + mt * 16 + (lg & 1) * 8 + l7;
#pragma unroll
    for (int p = 0; p < 2; ++p)    rowB[p] = wn * 32 + p * 16 + (lg >> 1) * 8 + l7;
    const int cA = lg >> 1;                            // A chunk offset
    const int cB = lg & 1;                             // B chunk offset

    load_tile(Asm, Bsm, Asrc, Bsrc, tid, ldA, ldB);
    cp_commit();
    load_tile(Asm + STAGE_BYTES, Bsm + STAGE_BYTES, Asrc + KC, Bsrc + KC,
              tid, ldA, ldB);
    cp_commit();

    for (int it = 0; it < T_; ++it) {
        cp_wait<1>();
        __syncthreads();   // single barrier/iter: also orders prior iter's reads
                           // before this iter's loads overwrite a retired stage
        if (it + 2 < T_) {
            int s = (it + 2) % STAGES;
            load_tile(Asm + s * STAGE_BYTES, Bsm + s * STAGE_BYTES,
                      Asrc + (size_t)(it + 2) * KC, Bsrc + (size_t)(it + 2) * KC,
                      tid, ldA, ldB);
        }
        cp_commit();
        uint32_t Ab = Asm + (it % STAGES) * STAGE_BYTES;
        uint32_t Bb = Bsm + (it % STAGES) * STAGE_BYTES;
#pragma unroll
        for (int kk = 0; kk < KC; kk += 16) {
            const int ck = kk >> 3;
            uint32_t af[4][4], bf[4][2];
#pragma unroll
            for (int mt = 0; mt < 4; ++mt)
                ldm_x4(af[mt], Ab + swz(rowA[mt], ck + cA));
#pragma unroll
            for (int p = 0; p < 2; ++p) {
                uint32_t t[4];
                ldm_x4(t, Bb + swz(rowB[p], ck + cB));
                bf[2 * p][0] = t[0];
                bf[2 * p][1] = t[1];
                bf[2 * p + 1][0] = t[2];
                bf[2 * p + 1][1] = t[3];
            }
#pragma unroll
            for (int mt = 0; mt < 4; ++mt)
#pragma unroll
                for (int nt = 0; nt < 4; ++nt) mma16(acc[mt][nt], af[mt], bf[nt]);
        }
    }
}

// ---------------------------------------------------------------- prep ------
__global__ void k_rnorm_m(const float* __restrict__ mem) {
    int m = blockIdx.x;
    const float* p = mem + m * C_;
    float acc = 0.f;
    for (int c = threadIdx.x; c < C_; c += 128) {
        float v = p[c];
        acc = fmaf(v, v, acc);
    }
#pragma unroll
    for (int o = 16; o; o >>= 1) acc += __shfl_xor_sync(0xffffffffu, acc, o);
    __shared__ float s[4];
    if ((threadIdx.x & 31) == 0) s[threadIdx.x >> 5] = acc;
    __syncthreads();
    if (threadIdx.x == 0)
        g_rm[m] = 1.0f / fmaxf(sqrtf(s[0] + s[1] + s[2] + s[3]), 1e-12f);
}

__global__ void k_prep(const float* __restrict__ mem) {
    __shared__ float t[32][33];
    int c0 = blockIdx.x << 5, m0 = blockIdx.y << 5;
    int tx = threadIdx.x, ty = threadIdx.y;
    float v = mem[(size_t)(m0 + ty) * C_ + c0 + tx];
    g_memh[(size_t)(m0 + ty) * C_ + c0 + tx] = __float2half_rn(v * g_rm[m0 + ty]);
    t[ty][tx] = v;
    __syncthreads();
    g_memTh[(size_t)(c0 + ty) * M_ + m0 + tx] = __float2half_rn(t[tx][ty]);
}

// zh[bn][c] = half(z[b,c,n] * rz[bn])  — fused transpose + L2 norm
__global__ void __launch_bounds__(256) k_zt_h(const float* __restrict__ z) {
    extern __shared__ float tile[];   // [768][33]
    __shared__ float part[8][32];
    __shared__ float rzv[32];
    int blk = blockIdx.x;
    int b = blk >> 7;
    int n0 = (blk & 127) << 5;
    const float* zb = z + (size_t)b * (C_ * N_) + n0;
    int tid = threadIdx.x;
    for (int e = tid; e < C_ * 32; e += 256) {
        int c = e >> 5, nl = e & 31;
        tile[c * 33 + nl] = zb[(size_t)c * N_ + nl];
    }
    __syncthreads();
    {
        int col = tid & 31, j = tid >> 5;
        float acc = 0.f;
        for (int c = j; c < C_; c += 8) {
            float v = tile[c * 33 + col];
            acc = fmaf(v, v, acc);
        }
        part[j][col] = acc;
    }
    __syncthreads();
    if (tid < 32) {
        float s = 0.f;
#pragma unroll
        for (int j = 0; j < 8; ++j) s += part[j][tid];
        rzv[tid] = 1.0f / fmaxf(sqrtf(s), 1e-12f);
    }
    __syncthreads();
    __half* out = g_zh + (size_t)(b * N_ + n0) * C_;
    for (int e = tid; e < C_ * 32; e += 256) {
        int nl = e / C_;
        int c = e - nl * C_;
        out[(size_t)nl * C_ + c] = __float2half_rn(tile[c * 33 + nl] * rzv[nl]);
    }
}

// ---------------------------------------------------------------- GEMM1 -----
// scores[row][m] = sum_c zh[row][c] * memh[m][c]
__global__ void __launch_bounds__(256, 2) k_gemm1_h(float* __restrict__ scores) {
    extern __shared__ __align__(128) char sm_[];
    const int tid = threadIdx.x, lane = tid & 31, warp = tid >> 5;
    const int g = lane >> 2, tg = lane & 3;
    const int wm = warp >> 2, wn = warp & 3;
    const int m0 = blockIdx.x * 128;
    const int row0 = blockIdx.y * 128;

    float acc[4][4][4];
    gemm_main(sm_, C_ / KC, g_zh + (size_t)row0 * C_, g_memh + (size_t)m0 * C_,
              C_, C_, tid, wm, wn, lane, acc);

#pragma unroll
    for (int mt = 0; mt < 4; ++mt) {
        int r = row0 + wm * 64 + mt * 16 + g;
#pragma unroll
        for (int nt = 0; nt < 4; ++nt) {
            int col = m0 + wn * 32 + nt * 8 + 2 * tg;
            float2 o;
            o.x = acc[mt][nt][0];
            o.y = acc[mt][nt][1];
            *(float2*)(scores + (size_t)r * M_ + col) = o;
            o.x = acc[mt][nt][2];
            o.y = acc[mt][nt][3];
            *(float2*)(scores + (size_t)(r + 8) * M_ + col) = o;
        }
    }
}

// ---------------------------------------------------------------- GEMM2 -----
// zhat[b,c,n] = sum_m attnh[row][m] * memTh[c][m]
// Epilogue transposes through smem (reusing pipeline smem) for coalesced n-writes.
__global__ void __launch_bounds__(256, 2) k_gemm2_h(float* __restrict__ zhat) {
    extern __shared__ __align__(128) char sm_[];
    const int tid = threadIdx.x, lane = tid & 31, warp = tid >> 5;
    const int g = lane >> 2, tg = lane & 3;
    const int wm = warp >> 2, wn = warp & 3;
    const int c0 = blockIdx.x * 128;
    const int row0 = blockIdx.y * 128;

    float acc[4][4][4];
    gemm_main(sm_, M_ / KC, g_attnh + (size_t)row0 * M_, g_memTh + (size_t)c0 * M_,
              M_, M_, tid, wm, wn, lane, acc);

    __syncthreads();   // mainloop smem reads done; reuse as transpose staging
    float* smf = (float*)sm_;          // [128 cols][132] = 67584 B < 96 KB
#pragma unroll
    for (int mt = 0; mt < 4; ++mt) {
        int r = wm * 64 + mt * 16 + g;
#pragma unroll
        for (int nt = 0; nt < 4; ++nt) {
            int col = wn * 32 + nt * 8 + 2 * tg;
            smf[(size_t)col * 132 + r]           = acc[mt][nt][0];
            smf[(size_t)(col + 1) * 132 + r]     = acc[mt][nt][1];
            smf[(size_t)col * 132 + r + 8]       = acc[mt][nt][2];
            smf[(size_t)(col + 1) * 132 + r + 8] = acc[mt][nt][3];
        }
    }
    __syncthreads();

    const int b = row0 >> 12;
    const int n0 = row0 & (N_ - 1);
    float* base = zhat + (size_t)b * (C_ * N_) + n0;
    // 128 cols x 128 n-floats; 32 float4 per col, fully coalesced
#pragma unroll
    for (int p = 0; p < 16; ++p) {
        int e = p * 256 + tid;
        int cc = e >> 5, q4 = e & 31;
        float4 v = *(const float4*)(smf + (size_t)cc * 132 + q4 * 4);
        *(float4*)(base + (size_t)(c0 + cc) * N_ + q4 * 4) = v;
    }
}

// ---------------------------------------------------------------- softmax ---
// float attn (exact output to d_out) + half copy for GEMM2
__global__ void k_softmax(float* __restrict__ attn) {
    const size_t row = blockIdx.x;
    float* p = attn + row * M_;
    const int t = threadIdx.x;
    float v[8];
    *(float4*)(v)     = *(const float4*)(p + t * 8);
    *(float4*)(v + 4) = *(const float4*)(p + t * 8 + 4);
    float mx = v[0];
#pragma unroll
    for (int i = 1; i < 8; ++i) mx = fmaxf(mx, v[i]);
#pragma unroll
    for (int o = 16; o; o >>= 1) mx = fmaxf(mx, __shfl_xor_sync(0xffffffffu, mx, o));
    __shared__ float red[4];
    if ((t & 31) == 0) red[t >> 5] = mx;
    __syncthreads();
    mx = fmaxf(fmaxf(red[0], red[1]), fmaxf(red[2], red[3]));
    __syncthreads();
    float sum = 0.f;
#pragma unroll
    for (int i = 0; i < 8; ++i) {
        v[i] = expf(v[i] - mx);
        sum += v[i];
    }
#pragma unroll
    for (int o = 16; o; o >>= 1) sum += __shfl_xor_sync(0xffffffffu, sum, o);
    if ((t & 31) == 0) red[t >> 5] = sum;
    __syncthreads();
    sum = red[0] + red[1] + red[2] + red[3];
    float r = 1.0f / sum;
#pragma unroll
    for (int i = 0; i < 8; ++i) v[i] *= r;
    *(float4*)(p + t * 8)     = *(const float4*)(v);
    *(float4*)(p + t * 8 + 4) = *(const float4*)(v + 4);
    __half2 h0 = __floats2half2_rn(v[0], v[1]);
    __half2 h1 = __floats2half2_rn(v[2], v[3]);
    __half2 h2 = __floats2half2_rn(v[4], v[5]);
    __half2 h3 = __floats2half2_rn(v[6], v[7]);
    uint4 u;
    u.x = *(uint32_t*)&h0;
    u.y = *(uint32_t*)&h1;
    u.z = *(uint32_t*)&h2;
    u.w = *(uint32_t*)&h3;
    *(uint4*)(g_attnh + row * M_ + t * 8) = u;
}

// ---------------------------------------------------------------------------
extern "C" void kernel_launch(void* const* d_in, const int* in_sizes, int n_in,
                              void* d_out, int out_size) {
    const float* z   = (const float*)d_in[0];
    const float* mem = (const float*)d_in[1];
    float* zhat = (float*)d_out;
    float* attn = zhat + (size_t)B_ * C_ * N_;

    cudaFuncSetAttribute(k_zt_h, cudaFuncAttributeMaxDynamicSharedMemorySize, C_ * 33 * 4);
    cudaFuncSetAttribute(k_gemm1_h, cudaFuncAttributeMaxDynamicSharedMemorySize, DYN_SMEM);
    cudaFuncSetAttribute(k_gemm2_h, cudaFuncAttributeMaxDynamicSharedMemorySize, DYN_SMEM);

    k_rnorm_m<<<M_, 128>>>(mem);
    k_prep<<<dim3(C_ / 32, M_ / 32), dim3(32, 32)>>>(mem);
    k_zt_h<<<BN_ / 32, 256, C_ * 33 * 4>>>(z);
    k_gemm1_h<<<dim3(M_ / 128, BN_ / 128), 256, DYN_SMEM>>>(attn);
    k_softmax<<<BN_, 128>>>(attn);
    k_gemm2_h<<<dim3(C_ / 128, BN_ / 128), 256, DYN_SMEM>>>(zhat);
}

// round 9
// speedup vs baseline: 1.1103x; 1.0161x over previous
#include <cuda_runtime.h>
#include <cuda_fp16.h>
#include <math.h>
#include <stdint.h>

#define B_  16
#define C_  768
#define N_  4096
#define BN_ 65536
#define M_  1024

#define KC      64                   // K halves per pipeline chunk (4 x k16 mma)
#define STAGES  3
#define STAGE_BYTES (128 * 128)      // 128 rows x 64 halves, swizzled, no pad
#define DYN_SMEM (STAGES * 2 * STAGE_BYTES)   // 98304 B -> 2 CTAs/SM
#define NT_GEMM 128                  // threads per GEMM CTA (4 warps, 2x2)

// scratch (allocation-free __device__ globals)
__device__ __half g_zh[(size_t)BN_ * C_];     // half(z * rz), K-major [bn][c]
__device__ __half g_memh[M_ * C_];            // half(mem * rm)        [m][c]
__device__ __half g_memTh[C_ * M_];           // half(mem) transposed  [c][m]
__device__ __half g_attnh[(size_t)BN_ * M_];  // half(attn)            [bn][m]
__device__ float  g_rm[M_];

// ---------------------------------------------------------------- helpers ---
__device__ __forceinline__ uint32_t smem_u32(const void* p) {
    uint32_t a;
    asm("{ .reg .u64 t; cvta.to.shared.u64 t, %1; cvt.u32.u64 %0, t; }"
        : "=r"(a) : "l"(p));
    return a;
}
__device__ __forceinline__ void cp16(uint32_t dst, const void* src) {
    asm volatile("cp.async.cg.shared.global [%0], [%1], 16;" :: "r"(dst), "l"(src));
}
__device__ __forceinline__ void cp_commit() {
    asm volatile("cp.async.commit_group;\n" ::: "memory");
}
template <int W>
__device__ __forceinline__ void cp_wait() {
    asm volatile("cp.async.wait_group %0;\n" :: "n"(W) : "memory");
}
__device__ __forceinline__ void mma16(float* d, const uint32_t* a, const uint32_t* b) {
    asm volatile(
        "mma.sync.aligned.m16n8k16.row.col.f32.f16.f16.f32 "
        "{%0,%1,%2,%3}, {%4,%5,%6,%7}, {%8,%9}, {%0,%1,%2,%3};\n"
        : "+f"(d[0]), "+f"(d[1]), "+f"(d[2]), "+f"(d[3])
        : "r"(a[0]), "r"(a[1]), "r"(a[2]), "r"(a[3]), "r"(b[0]), "r"(b[1]));
}
__device__ __forceinline__ void ldm_x4(uint32_t* r, uint32_t addr) {
    asm volatile("ldmatrix.sync.aligned.m8n8.x4.shared.b16 {%0,%1,%2,%3}, [%4];"
                 : "=r"(r[0]), "=r"(r[1]), "=r"(r[2]), "=r"(r[3]) : "r"(addr));
}
// swizzled physical byte offset: row r (stride 128B), 16B chunk c -> c ^ (r&7)
__device__ __forceinline__ uint32_t swz(int r, int c) {
    return (uint32_t)(r * 128) + (uint32_t)((c ^ (r & 7)) << 4);
}

// stage loader (128 threads): 128 rows x KC halves for A and B
__device__ __forceinline__ void load_tile(uint32_t dstA, uint32_t dstB,
                                          const __half* srcA, const __half* srcB,
                                          int tid, int ldA, int ldB) {
#pragma unroll
    for (int q = 0; q < 8; ++q) {
        int e = q * NT_GEMM + tid;
        int r = e >> 3, kq = e & 7;
        cp16(dstA + swz(r, kq), srcA + (size_t)r * ldA + kq * 8);
    }
#pragma unroll
    for (int q = 0; q < 8; ++q) {
        int e = q * NT_GEMM + tid;
        int r = e >> 3, kq = e & 7;
        cp16(dstB + swz(r, kq), srcB + (size_t)r * ldB + kq * 8);
    }
}

// ------------------------------------------------------------- GEMM core ----
// D[128 x 128] = A[128 x K] * B[128 x K]^T, fp16 in, fp32 acc.
// 4 warps as 2x2; warp tile 64x64; 3-stage cp.async pipeline; ldmatrix frags;
// single barrier per iteration.
__device__ __forceinline__ void gemm_main(char* sm_, int T_,
                                          const __half* Asrc, const __half* Bsrc,
                                          int ldA, int ldB, int tid,
                                          int wm, int wn, int lane,
                                          float acc[4][8][4]) {
#pragma unroll
    for (int i = 0; i < 4; ++i)
#pragma unroll
        for (int j = 0; j < 8; ++j)
#pragma unroll
            for (int q = 0; q < 4; ++q) acc[i][j][q] = 0.f;

    uint32_t Asm = smem_u32(sm_);
    uint32_t Bsm = Asm + STAGES * STAGE_BYTES;

    const int l7 = lane & 7, lg = lane >> 3;          // lg: 0..3
    int rowA[4], rowB[4];
#pragma unroll
    for (int mt = 0; mt < 4; ++mt) rowA[mt] = wm * 64 + mt * 16 + (lg & 1) * 8 + l7;
#pragma unroll
    for (int p = 0; p < 4; ++p)    rowB[p] = wn * 64 + p * 16 + (lg >> 1) * 8 + l7;
    const int cA = lg >> 1;                            // A chunk offset
    const int cB = lg & 1;                             // B chunk offset

    load_tile(Asm, Bsm, Asrc, Bsrc, tid, ldA, ldB);
    cp_commit();
    load_tile(Asm + STAGE_BYTES, Bsm + STAGE_BYTES, Asrc + KC, Bsrc + KC,
              tid, ldA, ldB);
    cp_commit();

    for (int it = 0; it < T_; ++it) {
        cp_wait<1>();
        __syncthreads();   // single barrier/iter; guards data + stage reuse
        if (it + 2 < T_) {
            int s = (it + 2) % STAGES;
            load_tile(Asm + s * STAGE_BYTES, Bsm + s * STAGE_BYTES,
                      Asrc + (size_t)(it + 2) * KC, Bsrc + (size_t)(it + 2) * KC,
                      tid, ldA, ldB);
        }
        cp_commit();
        uint32_t Ab = Asm + (it % STAGES) * STAGE_BYTES;
        uint32_t Bb = Bsm + (it % STAGES) * STAGE_BYTES;
#pragma unroll
        for (int kk = 0; kk < KC; kk += 16) {
            const int ck = kk >> 3;
            uint32_t af[4][4], bf[8][2];
#pragma unroll
            for (int mt = 0; mt < 4; ++mt)
                ldm_x4(af[mt], Ab + swz(rowA[mt], ck + cA));
#pragma unroll
            for (int p = 0; p < 4; ++p) {
                uint32_t t[4];
                ldm_x4(t, Bb + swz(rowB[p], ck + cB));
                bf[2 * p][0] = t[0];
                bf[2 * p][1] = t[1];
                bf[2 * p + 1][0] = t[2];
                bf[2 * p + 1][1] = t[3];
            }
#pragma unroll
            for (int mt = 0; mt < 4; ++mt)
#pragma unroll
                for (int nt = 0; nt < 8; ++nt) mma16(acc[mt][nt], af[mt], bf[nt]);
        }
    }
}

// ---------------------------------------------------------------- prep ------
__global__ void k_rnorm_m(const float* __restrict__ mem) {
    int m = blockIdx.x;
    const float* p = mem + m * C_;
    float acc = 0.f;
    for (int c = threadIdx.x; c < C_; c += 128) {
        float v = p[c];
        acc = fmaf(v, v, acc);
    }
#pragma unroll
    for (int o = 16; o; o >>= 1) acc += __shfl_xor_sync(0xffffffffu, acc, o);
    __shared__ float s[4];
    if ((threadIdx.x & 31) == 0) s[threadIdx.x >> 5] = acc;
    __syncthreads();
    if (threadIdx.x == 0)
        g_rm[m] = 1.0f / fmaxf(sqrtf(s[0] + s[1] + s[2] + s[3]), 1e-12f);
}

__global__ void k_prep(const float* __restrict__ mem) {
    __shared__ float t[32][33];
    int c0 = blockIdx.x << 5, m0 = blockIdx.y << 5;
    int tx = threadIdx.x, ty = threadIdx.y;
    float v = mem[(size_t)(m0 + ty) * C_ + c0 + tx];
    g_memh[(size_t)(m0 + ty) * C_ + c0 + tx] = __float2half_rn(v * g_rm[m0 + ty]);
    t[ty][tx] = v;
    __syncthreads();
    g_memTh[(size_t)(c0 + ty) * M_ + m0 + tx] = __float2half_rn(t[tx][ty]);
}

// zh[bn][c] = half(z[b,c,n] * rz[bn])  — fused transpose + L2 norm
__global__ void __launch_bounds__(256) k_zt_h(const float* __restrict__ z) {
    extern __shared__ float tile[];   // [768][33]
    __shared__ float part[8][32];
    __shared__ float rzv[32];
    int blk = blockIdx.x;
    int b = blk >> 7;
    int n0 = (blk & 127) << 5;
    const float* zb = z + (size_t)b * (C_ * N_) + n0;
    int tid = threadIdx.x;
    for (int e = tid; e < C_ * 32; e += 256) {
        int c = e >> 5, nl = e & 31;
        tile[c * 33 + nl] = zb[(size_t)c * N_ + nl];
    }
    __syncthreads();
    {
        int col = tid & 31, j = tid >> 5;
        float acc = 0.f;
        for (int c = j; c < C_; c += 8) {
            float v = tile[c * 33 + col];
            acc = fmaf(v, v, acc);
        }
        part[j][col] = acc;
    }
    __syncthreads();
    if (tid < 32) {
        float s = 0.f;
#pragma unroll
        for (int j = 0; j < 8; ++j) s += part[j][tid];
        rzv[tid] = 1.0f / fmaxf(sqrtf(s), 1e-12f);
    }
    __syncthreads();
    __half* out = g_zh + (size_t)(b * N_ + n0) * C_;
    for (int e = tid; e < C_ * 32; e += 256) {
        int nl = e / C_;
        int c = e - nl * C_;
        out[(size_t)nl * C_ + c] = __float2half_rn(tile[c * 33 + nl] * rzv[nl]);
    }
}

// ---------------------------------------------------------------- GEMM1 -----
// scores[row][m] = sum_c zh[row][c] * memh[m][c]
__global__ void __launch_bounds__(NT_GEMM, 2) k_gemm1_h(float* __restrict__ scores) {
    extern __shared__ __align__(128) char sm_[];
    const int tid = threadIdx.x, lane = tid & 31, warp = tid >> 5;
    const int g = lane >> 2, tg = lane & 3;
    const int wm = warp >> 1, wn = warp & 1;
    const int m0 = blockIdx.x * 128;
    const int row0 = blockIdx.y * 128;

    float acc[4][8][4];
    gemm_main(sm_, C_ / KC, g_zh + (size_t)row0 * C_, g_memh + (size_t)m0 * C_,
              C_, C_, tid, wm, wn, lane, acc);

#pragma unroll
    for (int mt = 0; mt < 4; ++mt) {
        int r = row0 + wm * 64 + mt * 16 + g;
#pragma unroll
        for (int nt = 0; nt < 8; ++nt) {
            int col = m0 + wn * 64 + nt * 8 + 2 * tg;
            float2 o;
            o.x = acc[mt][nt][0];
            o.y = acc[mt][nt][1];
            *(float2*)(scores + (size_t)r * M_ + col) = o;
            o.x = acc[mt][nt][2];
            o.y = acc[mt][nt][3];
            *(float2*)(scores + (size_t)(r + 8) * M_ + col) = o;
        }
    }
}

// ---------------------------------------------------------------- GEMM2 -----
// zhat[b,c,n] = sum_m attnh[row][m] * memTh[c][m]
// Epilogue transposes through smem (reusing pipeline smem) for coalesced n-writes.
__global__ void __launch_bounds__(NT_GEMM, 2) k_gemm2_h(float* __restrict__ zhat) {
    extern __shared__ __align__(128) char sm_[];
    const int tid = threadIdx.x, lane = tid & 31, warp = tid >> 5;
    const int g = lane >> 2, tg = lane & 3;
    const int wm = warp >> 1, wn = warp & 1;
    const int c0 = blockIdx.x * 128;
    const int row0 = blockIdx.y * 128;

    float acc[4][8][4];
    gemm_main(sm_, M_ / KC, g_attnh + (size_t)row0 * M_, g_memTh + (size_t)c0 * M_,
              M_, M_, tid, wm, wn, lane, acc);

    __syncthreads();   // mainloop smem reads done; reuse as transpose staging
    float* smf = (float*)sm_;          // [128 cols][132] = 67584 B < 96 KB
#pragma unroll
    for (int mt = 0; mt < 4; ++mt) {
        int r = wm * 64 + mt * 16 + g;
#pragma unroll
        for (int nt = 0; nt < 8; ++nt) {
            int col = wn * 64 + nt * 8 + 2 * tg;
            smf[(size_t)col * 132 + r]           = acc[mt][nt][0];
            smf[(size_t)(col + 1) * 132 + r]     = acc[mt][nt][1];
            smf[(size_t)col * 132 + r + 8]       = acc[mt][nt][2];
            smf[(size_t)(col + 1) * 132 + r + 8] = acc[mt][nt][3];
        }
    }
    __syncthreads();

    const int b = row0 >> 12;
    const int n0 = row0 & (N_ - 1);
    float* base = zhat + (size_t)b * (C_ * N_) + n0;
    // 128 cols x 128 n-floats; 32 float4 per col, fully coalesced
#pragma unroll
    for (int p = 0; p < 32; ++p) {
        int e = p * NT_GEMM + tid;
        int cc = e >> 5, q4 = e & 31;
        float4 v = *(const float4*)(smf + (size_t)cc * 132 + q4 * 4);
        *(float4*)(base + (size_t)(c0 + cc) * N_ + q4 * 4) = v;
    }
}

// ---------------------------------------------------------------- softmax ---
// float attn (exact output to d_out) + half copy for GEMM2
__global__ void k_softmax(float* __restrict__ attn) {
    const size_t row = blockIdx.x;
    float* p = attn + row * M_;
    const int t = threadIdx.x;
    float v[8];
    *(float4*)(v)     = *(const float4*)(p + t * 8);
    *(float4*)(v + 4) = *(const float4*)(p + t * 8 + 4);
    float mx = v[0];
#pragma unroll
    for (int i = 1; i < 8; ++i) mx = fmaxf(mx, v[i]);
#pragma unroll
    for (int o = 16; o; o >>= 1) mx = fmaxf(mx, __shfl_xor_sync(0xffffffffu, mx, o));
    __shared__ float red[4];
    if ((t & 31) == 0) red[t >> 5] = mx;
    __syncthreads();
    mx = fmaxf(fmaxf(red[0], red[1]), fmaxf(red[2], red[3]));
    __syncthreads();
    float sum = 0.f;
#pragma unroll
    for (int i = 0; i < 8; ++i) {
        v[i] = expf(v[i] - mx);
        sum += v[i];
    }
#pragma unroll
    for (int o = 16; o; o >>= 1) sum += __shfl_xor_sync(0xffffffffu, sum, o);
    if ((t & 31) == 0) red[t >> 5] = sum;
    __syncthreads();
    sum = red[0] + red[1] + red[2] + red[3];
    float r = 1.0f / sum;
#pragma unroll
    for (int i = 0; i < 8; ++i) v[i] *= r;
    *(float4*)(p + t * 8)     = *(const float4*)(v);
    *(float4*)(p + t * 8 + 4) = *(const float4*)(v + 4);
    __half2 h0 = __floats2half2_rn(v[0], v[1]);
    __half2 h1 = __floats2half2_rn(v[2], v[3]);
    __half2 h2 = __floats2half2_rn(v[4], v[5]);
    __half2 h3 = __floats2half2_rn(v[6], v[7]);
    uint4 u;
    u.x = *(uint32_t*)&h0;
    u.y = *(uint32_t*)&h1;
    u.z = *(uint32_t*)&h2;
    u.w = *(uint32_t*)&h3;
    *(uint4*)(g_attnh + row * M_ + t * 8) = u;
}

// ---------------------------------------------------------------------------
extern "C" void kernel_launch(void* const* d_in, const int* in_sizes, int n_in,
                              void* d_out, int out_size) {
    const float* z   = (const float*)d_in[0];
    const float* mem = (const float*)d_in[1];
    float* zhat = (float*)d_out;
    float* attn = zhat + (size_t)B_ * C_ * N_;

    cudaFuncSetAttribute(k_zt_h, cudaFuncAttributeMaxDynamicSharedMemorySize, C_ * 33 * 4);
    cudaFuncSetAttribute(k_gemm1_h, cudaFuncAttributeMaxDynamicSharedMemorySize, DYN_SMEM);
    cudaFuncSetAttribute(k_gemm2_h, cudaFuncAttributeMaxDynamicSharedMemorySize, DYN_SMEM);

    k_rnorm_m<<<M_, 128>>>(mem);
    k_prep<<<dim3(C_ / 32, M_ / 32), dim3(32, 32)>>>(mem);
    k_zt_h<<<BN_ / 32, 256, C_ * 33 * 4>>>(z);
    k_gemm1_h<<<dim3(M_ / 128, BN_ / 128), NT_GEMM, DYN_SMEM>>>(attn);
    k_softmax<<<BN_, 128>>>(attn);
    k_gemm2_h<<<dim3(C_ / 128, BN_ / 128), NT_GEMM, DYN_SMEM>>>(zhat);
}

// round 10
// speedup vs baseline: 1.1346x; 1.0218x over previous
#include <cuda_runtime.h>
#include <cuda_fp16.h>
#include <math.h>
#include <stdint.h>

#define B_  16
#define C_  768
#define N_  4096
#define BN_ 65536
#define M_  1024

#define KC      64                   // K halves per pipeline chunk (4 x k16 mma)
#define STAGES  3
#define STAGE_BYTES (128 * 128)      // 128 rows x 64 halves, swizzled, no pad
#define DYN_SMEM (STAGES * 2 * STAGE_BYTES)   // 98304 B -> 2 CTAs/SM
#define NT_GEMM 128                  // threads per GEMM CTA (4 warps, 2x2)

// scratch (allocation-free __device__ globals)
__device__ __half g_zh[(size_t)BN_ * C_];     // half(z * rz), K-major [bn][c]
__device__ __half g_memh[M_ * C_];            // half(mem * rm)        [m][c]
__device__ __half g_memTh[C_ * M_];           // half(mem) transposed  [c][m]
__device__ __half g_attnh[(size_t)BN_ * M_];  // half scores, then half attn
__device__ float  g_rm[M_];

// ---------------------------------------------------------------- helpers ---
__device__ __forceinline__ uint32_t smem_u32(const void* p) {
    uint32_t a;
    asm("{ .reg .u64 t; cvta.to.shared.u64 t, %1; cvt.u32.u64 %0, t; }"
        : "=r"(a) : "l"(p));
    return a;
}
__device__ __forceinline__ void cp16(uint32_t dst, const void* src) {
    asm volatile("cp.async.cg.shared.global [%0], [%1], 16;" :: "r"(dst), "l"(src));
}
__device__ __forceinline__ void cp_commit() {
    asm volatile("cp.async.commit_group;\n" ::: "memory");
}
template <int W>
__device__ __forceinline__ void cp_wait() {
    asm volatile("cp.async.wait_group %0;\n" :: "n"(W) : "memory");
}
__device__ __forceinline__ void mma16(float* d, const uint32_t* a, const uint32_t* b) {
    asm volatile(
        "mma.sync.aligned.m16n8k16.row.col.f32.f16.f16.f32 "
        "{%0,%1,%2,%3}, {%4,%5,%6,%7}, {%8,%9}, {%0,%1,%2,%3};\n"
        : "+f"(d[0]), "+f"(d[1]), "+f"(d[2]), "+f"(d[3])
        : "r"(a[0]), "r"(a[1]), "r"(a[2]), "r"(a[3]), "r"(b[0]), "r"(b[1]));
}
__device__ __forceinline__ void ldm_x4(uint32_t* r, uint32_t addr) {
    asm volatile("ldmatrix.sync.aligned.m8n8.x4.shared.b16 {%0,%1,%2,%3}, [%4];"
                 : "=r"(r[0]), "=r"(r[1]), "=r"(r[2]), "=r"(r[3]) : "r"(addr));
}
// swizzled physical byte offset: row r (stride 128B), 16B chunk c -> c ^ (r&7)
__device__ __forceinline__ uint32_t swz(int r, int c) {
    return (uint32_t)(r * 128) + (uint32_t)((c ^ (r & 7)) << 4);
}

// stage loader (128 threads): 128 rows x KC halves for A and B
__device__ __forceinline__ void load_tile(uint32_t dstA, uint32_t dstB,
                                          const __half* srcA, const __half* srcB,
                                          int tid, int ldA, int ldB) {
#pragma unroll
    for (int q = 0; q < 8; ++q) {
        int e = q * NT_GEMM + tid;
        int r = e >> 3, kq = e & 7;
        cp16(dstA + swz(r, kq), srcA + (size_t)r * ldA + kq * 8);
    }
#pragma unroll
    for (int q = 0; q < 8; ++q) {
        int e = q * NT_GEMM + tid;
        int r = e >> 3, kq = e & 7;
        cp16(dstB + swz(r, kq), srcB + (size_t)r * ldB + kq * 8);
    }
}

// ------------------------------------------------------------- GEMM core ----
// D[128 x 128] = A[128 x K] * B[128 x K]^T, fp16 in, fp32 acc.
// 4 warps as 2x2; warp tile 64x64; 3-stage cp.async pipeline; ldmatrix frags;
// single barrier per iteration.
__device__ __forceinline__ void gemm_main(char* sm_, int T_,
                                          const __half* Asrc, const __half* Bsrc,
                                          int ldA, int ldB, int tid,
                                          int wm, int wn, int lane,
                                          float acc[4][8][4]) {
#pragma unroll
    for (int i = 0; i < 4; ++i)
#pragma unroll
        for (int j = 0; j < 8; ++j)
#pragma unroll
            for (int q = 0; q < 4; ++q) acc[i][j][q] = 0.f;

    uint32_t Asm = smem_u32(sm_);
    uint32_t Bsm = Asm + STAGES * STAGE_BYTES;

    const int l7 = lane & 7, lg = lane >> 3;          // lg: 0..3
    int rowA[4], rowB[4];
#pragma unroll
    for (int mt = 0; mt < 4; ++mt) rowA[mt] = wm * 64 + mt * 16 + (lg & 1) * 8 + l7;
#pragma unroll
    for (int p = 0; p < 4; ++p)    rowB[p] = wn * 64 + p * 16 + (lg >> 1) * 8 + l7;
    const int cA = lg >> 1;                            // A chunk offset
    const int cB = lg & 1;                             // B chunk offset

    load_tile(Asm, Bsm, Asrc, Bsrc, tid, ldA, ldB);
    cp_commit();
    load_tile(Asm + STAGE_BYTES, Bsm + STAGE_BYTES, Asrc + KC, Bsrc + KC,
              tid, ldA, ldB);
    cp_commit();

    for (int it = 0; it < T_; ++it) {
        cp_wait<1>();
        __syncthreads();   // single barrier/iter; guards data + stage reuse
        if (it + 2 < T_) {
            int s = (it + 2) % STAGES;
            load_tile(Asm + s * STAGE_BYTES, Bsm + s * STAGE_BYTES,
                      Asrc + (size_t)(it + 2) * KC, Bsrc + (size_t)(it + 2) * KC,
                      tid, ldA, ldB);
        }
        cp_commit();
        uint32_t Ab = Asm + (it % STAGES) * STAGE_BYTES;
        uint32_t Bb = Bsm + (it % STAGES) * STAGE_BYTES;
#pragma unroll
        for (int kk = 0; kk < KC; kk += 16) {
            const int ck = kk >> 3;
            uint32_t af[4][4], bf[8][2];
#pragma unroll
            for (int mt = 0; mt < 4; ++mt)
                ldm_x4(af[mt], Ab + swz(rowA[mt], ck + cA));
#pragma unroll
            for (int p = 0; p < 4; ++p) {
                uint32_t t[4];
                ldm_x4(t, Bb + swz(rowB[p], ck + cB));
                bf[2 * p][0] = t[0];
                bf[2 * p][1] = t[1];
                bf[2 * p + 1][0] = t[2];
                bf[2 * p + 1][1] = t[3];
            }
#pragma unroll
            for (int mt = 0; mt < 4; ++mt)
#pragma unroll
                for (int nt = 0; nt < 8; ++nt) mma16(acc[mt][nt], af[mt], bf[nt]);
        }
    }
}

// ---------------------------------------------------------------- prep ------
__global__ void k_rnorm_m(const float* __restrict__ mem) {
    int m = blockIdx.x;
    const float* p = mem + m * C_;
    float acc = 0.f;
    for (int c = threadIdx.x; c < C_; c += 128) {
        float v = p[c];
        acc = fmaf(v, v, acc);
    }
#pragma unroll
    for (int o = 16; o; o >>= 1) acc += __shfl_xor_sync(0xffffffffu, acc, o);
    __shared__ float s[4];
    if ((threadIdx.x & 31) == 0) s[threadIdx.x >> 5] = acc;
    __syncthreads();
    if (threadIdx.x == 0)
        g_rm[m] = 1.0f / fmaxf(sqrtf(s[0] + s[1] + s[2] + s[3]), 1e-12f);
}

__global__ void k_prep(const float* __restrict__ mem) {
    __shared__ float t[32][33];
    int c0 = blockIdx.x << 5, m0 = blockIdx.y << 5;
    int tx = threadIdx.x, ty = threadIdx.y;
    float v = mem[(size_t)(m0 + ty) * C_ + c0 + tx];
    g_memh[(size_t)(m0 + ty) * C_ + c0 + tx] = __float2half_rn(v * g_rm[m0 + ty]);
    t[ty][tx] = v;
    __syncthreads();
    g_memTh[(size_t)(c0 + ty) * M_ + m0 + tx] = __float2half_rn(t[tx][ty]);
}

// zh[bn][c] = half(z[b,c,n] * rz[bn])  — fused transpose + L2 norm
__global__ void __launch_bounds__(256) k_zt_h(const float* __restrict__ z) {
    extern __shared__ float tile[];   // [768][33]
    __shared__ float part[8][32];
    __shared__ float rzv[32];
    int blk = blockIdx.x;
    int b = blk >> 7;
    int n0 = (blk & 127) << 5;
    const float* zb = z + (size_t)b * (C_ * N_) + n0;
    int tid = threadIdx.x;
    for (int e = tid; e < C_ * 32; e += 256) {
        int c = e >> 5, nl = e & 31;
        tile[c * 33 + nl] = zb[(size_t)c * N_ + nl];
    }
    __syncthreads();
    {
        int col = tid & 31, j = tid >> 5;
        float acc = 0.f;
        for (int c = j; c < C_; c += 8) {
            float v = tile[c * 33 + col];
            acc = fmaf(v, v, acc);
        }
        part[j][col] = acc;
    }
    __syncthreads();
    if (tid < 32) {
        float s = 0.f;
#pragma unroll
        for (int j = 0; j < 8; ++j) s += part[j][tid];
        rzv[tid] = 1.0f / fmaxf(sqrtf(s), 1e-12f);
    }
    __syncthreads();
    __half* out = g_zh + (size_t)(b * N_ + n0) * C_;
    for (int e = tid; e < C_ * 32; e += 256) {
        int nl = e / C_;
        int c = e - nl * C_;
        out[(size_t)nl * C_ + c] = __float2half_rn(tile[c * 33 + nl] * rzv[nl]);
    }
}

// ---------------------------------------------------------------- GEMM1 -----
// g_attnh[row][m] = half( sum_c zh[row][c] * memh[m][c] )   (half scores)
__global__ void __launch_bounds__(NT_GEMM, 2) k_gemm1_h() {
    extern __shared__ __align__(128) char sm_[];
    const int tid = threadIdx.x, lane = tid & 31, warp = tid >> 5;
    const int g = lane >> 2, tg = lane & 3;
    const int wm = warp >> 1, wn = warp & 1;
    const int m0 = blockIdx.x * 128;
    const int row0 = blockIdx.y * 128;

    float acc[4][8][4];
    gemm_main(sm_, C_ / KC, g_zh + (size_t)row0 * C_, g_memh + (size_t)m0 * C_,
              C_, C_, tid, wm, wn, lane, acc);

#pragma unroll
    for (int mt = 0; mt < 4; ++mt) {
        int r = row0 + wm * 64 + mt * 16 + g;
#pragma unroll
        for (int nt = 0; nt < 8; ++nt) {
            int col = m0 + wn * 64 + nt * 8 + 2 * tg;
            __half2 h0 = __floats2half2_rn(acc[mt][nt][0], acc[mt][nt][1]);
            __half2 h1 = __floats2half2_rn(acc[mt][nt][2], acc[mt][nt][3]);
            *(__half2*)(g_attnh + (size_t)r * M_ + col)       = h0;
            *(__half2*)(g_attnh + (size_t)(r + 8) * M_ + col) = h1;
        }
    }
}

// ---------------------------------------------------------------- GEMM2 -----
// zhat[b,c,n] = sum_m attnh[row][m] * memTh[c][m]
// Epilogue transposes through smem (reusing pipeline smem) for coalesced n-writes.
__global__ void __launch_bounds__(NT_GEMM, 2) k_gemm2_h(float* __restrict__ zhat) {
    extern __shared__ __align__(128) char sm_[];
    const int tid = threadIdx.x, lane = tid & 31, warp = tid >> 5;
    const int g = lane >> 2, tg = lane & 3;
    const int wm = warp >> 1, wn = warp & 1;
    const int c0 = blockIdx.x * 128;
    const int row0 = blockIdx.y * 128;

    float acc[4][8][4];
    gemm_main(sm_, M_ / KC, g_attnh + (size_t)row0 * M_, g_memTh + (size_t)c0 * M_,
              M_, M_, tid, wm, wn, lane, acc);

    __syncthreads();   // mainloop smem reads done; reuse as transpose staging
    float* smf = (float*)sm_;          // [128 cols][132] = 67584 B < 96 KB
#pragma unroll
    for (int mt = 0; mt < 4; ++mt) {
        int r = wm * 64 + mt * 16 + g;
#pragma unroll
        for (int nt = 0; nt < 8; ++nt) {
            int col = wn * 64 + nt * 8 + 2 * tg;
            smf[(size_t)col * 132 + r]           = acc[mt][nt][0];
            smf[(size_t)(col + 1) * 132 + r]     = acc[mt][nt][1];
            smf[(size_t)col * 132 + r + 8]       = acc[mt][nt][2];
            smf[(size_t)(col + 1) * 132 + r + 8] = acc[mt][nt][3];
        }
    }
    __syncthreads();

    const int b = row0 >> 12;
    const int n0 = row0 & (N_ - 1);
    float* base = zhat + (size_t)b * (C_ * N_) + n0;
#pragma unroll
    for (int p = 0; p < 32; ++p) {
        int e = p * NT_GEMM + tid;
        int cc = e >> 5, q4 = e & 31;
        float4 v = *(const float4*)(smf + (size_t)cc * 132 + q4 * 4);
        *(float4*)(base + (size_t)(c0 + cc) * N_ + q4 * 4) = v;
    }
}

// ---------------------------------------------------------------- softmax ---
// reads half scores from g_attnh, writes float attn to d_out and half attn
// back into g_attnh (in place; each block owns its row).
__global__ void k_softmax(float* __restrict__ attn) {
    const size_t row = blockIdx.x;
    const int t = threadIdx.x;
    float v[8];
    {
        uint4 u = *(const uint4*)(g_attnh + row * M_ + t * 8);
        __half2 h0 = *(__half2*)&u.x, h1 = *(__half2*)&u.y;
        __half2 h2 = *(__half2*)&u.z, h3 = *(__half2*)&u.w;
        float2 f0 = __half22float2(h0), f1 = __half22float2(h1);
        float2 f2 = __half22float2(h2), f3 = __half22float2(h3);
        v[0] = f0.x; v[1] = f0.y; v[2] = f1.x; v[3] = f1.y;
        v[4] = f2.x; v[5] = f2.y; v[6] = f3.x; v[7] = f3.y;
    }
    float mx = v[0];
#pragma unroll
    for (int i = 1; i < 8; ++i) mx = fmaxf(mx, v[i]);
#pragma unroll
    for (int o = 16; o; o >>= 1) mx = fmaxf(mx, __shfl_xor_sync(0xffffffffu, mx, o));
    __shared__ float red[4];
    if ((t & 31) == 0) red[t >> 5] = mx;
    __syncthreads();
    mx = fmaxf(fmaxf(red[0], red[1]), fmaxf(red[2], red[3]));
    __syncthreads();
    float sum = 0.f;
#pragma unroll
    for (int i = 0; i < 8; ++i) {
        v[i] = expf(v[i] - mx);
        sum += v[i];
    }
#pragma unroll
    for (int o = 16; o; o >>= 1) sum += __shfl_xor_sync(0xffffffffu, sum, o);
    if ((t & 31) == 0) red[t >> 5] = sum;
    __syncthreads();
    sum = red[0] + red[1] + red[2] + red[3];
    float r = 1.0f / sum;
#pragma unroll
    for (int i = 0; i < 8; ++i) v[i] *= r;
    float* p = attn + row * M_;
    *(float4*)(p + t * 8)     = *(const float4*)(v);
    *(float4*)(p + t * 8 + 4) = *(const float4*)(v + 4);
    __half2 h0 = __floats2half2_rn(v[0], v[1]);
    __half2 h1 = __floats2half2_rn(v[2], v[3]);
    __half2 h2 = __floats2half2_rn(v[4], v[5]);
    __half2 h3 = __floats2half2_rn(v[6], v[7]);
    uint4 u;
    u.x = *(uint32_t*)&h0;
    u.y = *(uint32_t*)&h1;
    u.z = *(uint32_t*)&h2;
    u.w = *(uint32_t*)&h3;
    *(uint4*)(g_attnh + row * M_ + t * 8) = u;
}

// ---------------------------------------------------------------------------
extern "C" void kernel_launch(void* const* d_in, const int* in_sizes, int n_in,
                              void* d_out, int out_size) {
    const float* z   = (const float*)d_in[0];
    const float* mem = (const float*)d_in[1];
    float* zhat = (float*)d_out;
    float* attn = zhat + (size_t)B_ * C_ * N_;

    cudaFuncSetAttribute(k_zt_h, cudaFuncAttributeMaxDynamicSharedMemorySize, C_ * 33 * 4);
    cudaFuncSetAttribute(k_gemm1_h, cudaFuncAttributeMaxDynamicSharedMemorySize, DYN_SMEM);
    cudaFuncSetAttribute(k_gemm2_h, cudaFuncAttributeMaxDynamicSharedMemorySize, DYN_SMEM);

    k_rnorm_m<<<M_, 128>>>(mem);
    k_prep<<<dim3(C_ / 32, M_ / 32), dim3(32, 32)>>>(mem);
    k_zt_h<<<BN_ / 32, 256, C_ * 33 * 4>>>(z);
    k_gemm1_h<<<dim3(M_ / 128, BN_ / 128), NT_GEMM, DYN_SMEM>>>();
    k_softmax<<<BN_, 128>>>(attn);
    k_gemm2_h<<<dim3(C_ / 128, BN_ / 128), NT_GEMM, DYN_SMEM>>>(zhat);
}

// round 11
// speedup vs baseline: 1.1361x; 1.0014x over previous
#include <cuda_runtime.h>
#include <cuda_fp16.h>
#include <math.h>
#include <stdint.h>

#define B_  16
#define C_  768
#define N_  4096
#define BN_ 65536
#define M_  1024

#define KC      64                   // K halves per pipeline chunk (4 x k16 mma)
#define STAGES  3
#define STAGE_BYTES (128 * 128)      // 128 rows x 64 halves, swizzled, no pad
#define DYN_SMEM (STAGES * 2 * STAGE_BYTES)   // 98304 B -> 2 CTAs/SM
#define NT_GEMM 128                  // threads per GEMM CTA (4 warps, 2x2)

// scratch (allocation-free __device__ globals)
__device__ __half g_zh[(size_t)BN_ * C_];     // half(z * rz), K-major [bn][c]
__device__ __half g_memh[M_ * C_];            // half(mem * rm)        [m][c]
__device__ __half g_memTh[C_ * M_];           // half(mem) transposed  [c][m]
__device__ __half g_exph[(size_t)BN_ * M_];   // half exp(score)       [bn][m]
__device__ float  g_rsum[BN_];                // 1 / sum_m exp(score)
__device__ float  g_rm[M_];

// ---------------------------------------------------------------- helpers ---
__device__ __forceinline__ uint32_t smem_u32(const void* p) {
    uint32_t a;
    asm("{ .reg .u64 t; cvta.to.shared.u64 t, %1; cvt.u32.u64 %0, t; }"
        : "=r"(a) : "l"(p));
    return a;
}
__device__ __forceinline__ void cp16(uint32_t dst, const void* src) {
    asm volatile("cp.async.cg.shared.global [%0], [%1], 16;" :: "r"(dst), "l"(src));
}
__device__ __forceinline__ void cp_commit() {
    asm volatile("cp.async.commit_group;\n" ::: "memory");
}
template <int W>
__device__ __forceinline__ void cp_wait() {
    asm volatile("cp.async.wait_group %0;\n" :: "n"(W) : "memory");
}
__device__ __forceinline__ void mma16(float* d, const uint32_t* a, const uint32_t* b) {
    asm volatile(
        "mma.sync.aligned.m16n8k16.row.col.f32.f16.f16.f32 "
        "{%0,%1,%2,%3}, {%4,%5,%6,%7}, {%8,%9}, {%0,%1,%2,%3};\n"
        : "+f"(d[0]), "+f"(d[1]), "+f"(d[2]), "+f"(d[3])
        : "r"(a[0]), "r"(a[1]), "r"(a[2]), "r"(a[3]), "r"(b[0]), "r"(b[1]));
}
__device__ __forceinline__ void ldm_x4(uint32_t* r, uint32_t addr) {
    asm volatile("ldmatrix.sync.aligned.m8n8.x4.shared.b16 {%0,%1,%2,%3}, [%4];"
                 : "=r"(r[0]), "=r"(r[1]), "=r"(r[2]), "=r"(r[3]) : "r"(addr));
}
// swizzled physical byte offset: row r (stride 128B), 16B chunk c -> c ^ (r&7)
__device__ __forceinline__ uint32_t swz(int r, int c) {
    return (uint32_t)(r * 128) + (uint32_t)((c ^ (r & 7)) << 4);
}

// stage loader (128 threads): 128 rows x KC halves for A and B
__device__ __forceinline__ void load_tile(uint32_t dstA, uint32_t dstB,
                                          const __half* srcA, const __half* srcB,
                                          int tid, int ldA, int ldB) {
#pragma unroll
    for (int q = 0; q < 8; ++q) {
        int e = q * NT_GEMM + tid;
        int r = e >> 3, kq = e & 7;
        cp16(dstA + swz(r, kq), srcA + (size_t)r * ldA + kq * 8);
    }
#pragma unroll
    for (int q = 0; q < 8; ++q) {
        int e = q * NT_GEMM + tid;
        int r = e >> 3, kq = e & 7;
        cp16(dstB + swz(r, kq), srcB + (size_t)r * ldB + kq * 8);
    }
}

// ------------------------------------------------------------- GEMM core ----
// D[128 x 128] = A[128 x K] * B[128 x K]^T, fp16 in, fp32 acc.
// 4 warps as 2x2; warp tile 64x64; 3-stage cp.async pipeline; ldmatrix frags;
// single barrier per iteration.
__device__ __forceinline__ void gemm_main(char* sm_, int T_,
                                          const __half* Asrc, const __half* Bsrc,
                                          int ldA, int ldB, int tid,
                                          int wm, int wn, int lane,
                                          float acc[4][8][4]) {
#pragma unroll
    for (int i = 0; i < 4; ++i)
#pragma unroll
        for (int j = 0; j < 8; ++j)
#pragma unroll
            for (int q = 0; q < 4; ++q) acc[i][j][q] = 0.f;

    uint32_t Asm = smem_u32(sm_);
    uint32_t Bsm = Asm + STAGES * STAGE_BYTES;

    const int l7 = lane & 7, lg = lane >> 3;          // lg: 0..3
    int rowA[4], rowB[4];
#pragma unroll
    for (int mt = 0; mt < 4; ++mt) rowA[mt] = wm * 64 + mt * 16 + (lg & 1) * 8 + l7;
#pragma unroll
    for (int p = 0; p < 4; ++p)    rowB[p] = wn * 64 + p * 16 + (lg >> 1) * 8 + l7;
    const int cA = lg >> 1;                            // A chunk offset
    const int cB = lg & 1;                             // B chunk offset

    load_tile(Asm, Bsm, Asrc, Bsrc, tid, ldA, ldB);
    cp_commit();
    load_tile(Asm + STAGE_BYTES, Bsm + STAGE_BYTES, Asrc + KC, Bsrc + KC,
              tid, ldA, ldB);
    cp_commit();

    for (int it = 0; it < T_; ++it) {
        cp_wait<1>();
        __syncthreads();   // single barrier/iter; guards data + stage reuse
        if (it + 2 < T_) {
            int s = (it + 2) % STAGES;
            load_tile(Asm + s * STAGE_BYTES, Bsm + s * STAGE_BYTES,
                      Asrc + (size_t)(it + 2) * KC, Bsrc + (size_t)(it + 2) * KC,
                      tid, ldA, ldB);
        }
        cp_commit();
        uint32_t Ab = Asm + (it % STAGES) * STAGE_BYTES;
        uint32_t Bb = Bsm + (it % STAGES) * STAGE_BYTES;
#pragma unroll
        for (int kk = 0; kk < KC; kk += 16) {
            const int ck = kk >> 3;
            uint32_t af[4][4], bf[8][2];
#pragma unroll
            for (int mt = 0; mt < 4; ++mt)
                ldm_x4(af[mt], Ab + swz(rowA[mt], ck + cA));
#pragma unroll
            for (int p = 0; p < 4; ++p) {
                uint32_t t[4];
                ldm_x4(t, Bb + swz(rowB[p], ck + cB));
                bf[2 * p][0] = t[0];
                bf[2 * p][1] = t[1];
                bf[2 * p + 1][0] = t[2];
                bf[2 * p + 1][1] = t[3];
            }
#pragma unroll
            for (int mt = 0; mt < 4; ++mt)
#pragma unroll
                for (int nt = 0; nt < 8; ++nt) mma16(acc[mt][nt], af[mt], bf[nt]);
        }
    }
}

// ---------------------------------------------------------------- prep ------
__global__ void k_rnorm_m(const float* __restrict__ mem) {
    int m = blockIdx.x;
    const float* p = mem + m * C_;
    float acc = 0.f;
    for (int c = threadIdx.x; c < C_; c += 128) {
        float v = p[c];
        acc = fmaf(v, v, acc);
    }
#pragma unroll
    for (int o = 16; o; o >>= 1) acc += __shfl_xor_sync(0xffffffffu, acc, o);
    __shared__ float s[4];
    if ((threadIdx.x & 31) == 0) s[threadIdx.x >> 5] = acc;
    __syncthreads();
    if (threadIdx.x == 0)
        g_rm[m] = 1.0f / fmaxf(sqrtf(s[0] + s[1] + s[2] + s[3]), 1e-12f);
}

__global__ void k_prep(const float* __restrict__ mem) {
    __shared__ float t[32][33];
    int c0 = blockIdx.x << 5, m0 = blockIdx.y << 5;
    int tx = threadIdx.x, ty = threadIdx.y;
    float v = mem[(size_t)(m0 + ty) * C_ + c0 + tx];
    g_memh[(size_t)(m0 + ty) * C_ + c0 + tx] = __float2half_rn(v * g_rm[m0 + ty]);
    t[ty][tx] = v;
    __syncthreads();
    g_memTh[(size_t)(c0 + ty) * M_ + m0 + tx] = __float2half_rn(t[tx][ty]);
}

// zh[bn][c] = half(z[b,c,n] * rz[bn])  — fused transpose + L2 norm
__global__ void __launch_bounds__(256) k_zt_h(const float* __restrict__ z) {
    extern __shared__ float tile[];   // [768][33]
    __shared__ float part[8][32];
    __shared__ float rzv[32];
    int blk = blockIdx.x;
    int b = blk >> 7;
    int n0 = (blk & 127) << 5;
    const float* zb = z + (size_t)b * (C_ * N_) + n0;
    int tid = threadIdx.x;
    for (int e = tid; e < C_ * 32; e += 256) {
        int c = e >> 5, nl = e & 31;
        tile[c * 33 + nl] = zb[(size_t)c * N_ + nl];
    }
    __syncthreads();
    {
        int col = tid & 31, j = tid >> 5;
        float acc = 0.f;
        for (int c = j; c < C_; c += 8) {
            float v = tile[c * 33 + col];
            acc = fmaf(v, v, acc);
        }
        part[j][col] = acc;
    }
    __syncthreads();
    if (tid < 32) {
        float s = 0.f;
#pragma unroll
        for (int j = 0; j < 8; ++j) s += part[j][tid];
        rzv[tid] = 1.0f / fmaxf(sqrtf(s), 1e-12f);
    }
    __syncthreads();
    __half* out = g_zh + (size_t)(b * N_ + n0) * C_;
    for (int e = tid; e < C_ * 32; e += 256) {
        int nl = e / C_;
        int c = e - nl * C_;
        out[(size_t)nl * C_ + c] = __float2half_rn(tile[c * 33 + nl] * rzv[nl]);
    }
}

// ---------------------------------------------------------------- GEMM1 -----
// g_exph[row][m] = half( exp( sum_c zh[row][c] * memh[m][c] ) )
// (scores are cosines in [-1,1] -> exp is safe without max subtraction)
__global__ void __launch_bounds__(NT_GEMM, 2) k_gemm1_h() {
    extern __shared__ __align__(128) char sm_[];
    const int tid = threadIdx.x, lane = tid & 31, warp = tid >> 5;
    const int g = lane >> 2, tg = lane & 3;
    const int wm = warp >> 1, wn = warp & 1;
    const int m0 = blockIdx.x * 128;
    const int row0 = blockIdx.y * 128;

    float acc[4][8][4];
    gemm_main(sm_, C_ / KC, g_zh + (size_t)row0 * C_, g_memh + (size_t)m0 * C_,
              C_, C_, tid, wm, wn, lane, acc);

#pragma unroll
    for (int mt = 0; mt < 4; ++mt) {
        int r = row0 + wm * 64 + mt * 16 + g;
#pragma unroll
        for (int nt = 0; nt < 8; ++nt) {
            int col = m0 + wn * 64 + nt * 8 + 2 * tg;
            __half2 h0 = __floats2half2_rn(__expf(acc[mt][nt][0]),
                                           __expf(acc[mt][nt][1]));
            __half2 h1 = __floats2half2_rn(__expf(acc[mt][nt][2]),
                                           __expf(acc[mt][nt][3]));
            *(__half2*)(g_exph + (size_t)r * M_ + col)       = h0;
            *(__half2*)(g_exph + (size_t)(r + 8) * M_ + col) = h1;
        }
    }
}

// ---------------------------------------------------------------- finalize --
// reads half exp, computes rsum = 1/sum, writes float attn to d_out, stores rsum.
__global__ void k_finalize(float* __restrict__ attn) {
    const size_t row = blockIdx.x;
    const int t = threadIdx.x;
    float v[8];
    {
        uint4 u = *(const uint4*)(g_exph + row * M_ + t * 8);
        __half2 h0 = *(__half2*)&u.x, h1 = *(__half2*)&u.y;
        __half2 h2 = *(__half2*)&u.z, h3 = *(__half2*)&u.w;
        float2 f0 = __half22float2(h0), f1 = __half22float2(h1);
        float2 f2 = __half22float2(h2), f3 = __half22float2(h3);
        v[0] = f0.x; v[1] = f0.y; v[2] = f1.x; v[3] = f1.y;
        v[4] = f2.x; v[5] = f2.y; v[6] = f3.x; v[7] = f3.y;
    }
    float sum = 0.f;
#pragma unroll
    for (int i = 0; i < 8; ++i) sum += v[i];
#pragma unroll
    for (int o = 16; o; o >>= 1) sum += __shfl_xor_sync(0xffffffffu, sum, o);
    __shared__ float red[4];
    if ((t & 31) == 0) red[t >> 5] = sum;
    __syncthreads();
    sum = red[0] + red[1] + red[2] + red[3];
    float r = 1.0f / sum;
    if (t == 0) g_rsum[row] = r;
#pragma unroll
    for (int i = 0; i < 8; ++i) v[i] *= r;
    float* p = attn + row * M_;
    *(float4*)(p + t * 8)     = *(const float4*)(v);
    *(float4*)(p + t * 8 + 4) = *(const float4*)(v + 4);
}

// ---------------------------------------------------------------- GEMM2 -----
// zhat[b,c,n] = rsum[row] * sum_m exph[row][m] * memTh[c][m]
// Row scaling commutes with the m-contraction; applied in epilogue.
__global__ void __launch_bounds__(NT_GEMM, 2) k_gemm2_h(float* __restrict__ zhat) {
    extern __shared__ __align__(128) char sm_[];
    const int tid = threadIdx.x, lane = tid & 31, warp = tid >> 5;
    const int g = lane >> 2, tg = lane & 3;
    const int wm = warp >> 1, wn = warp & 1;
    const int c0 = blockIdx.x * 128;
    const int row0 = blockIdx.y * 128;

    float acc[4][8][4];
    gemm_main(sm_, M_ / KC, g_exph + (size_t)row0 * M_, g_memTh + (size_t)c0 * M_,
              M_, M_, tid, wm, wn, lane, acc);

    __syncthreads();   // mainloop smem reads done; reuse as transpose staging
    float* smf = (float*)sm_;          // [128 cols][132] = 67584 B < 96 KB
#pragma unroll
    for (int mt = 0; mt < 4; ++mt) {
        int r = wm * 64 + mt * 16 + g;
        float rs0 = g_rsum[row0 + r];
        float rs1 = g_rsum[row0 + r + 8];
#pragma unroll
        for (int nt = 0; nt < 8; ++nt) {
            int col = wn * 64 + nt * 8 + 2 * tg;
            smf[(size_t)col * 132 + r]           = acc[mt][nt][0] * rs0;
            smf[(size_t)(col + 1) * 132 + r]     = acc[mt][nt][1] * rs0;
            smf[(size_t)col * 132 + r + 8]       = acc[mt][nt][2] * rs1;
            smf[(size_t)(col + 1) * 132 + r + 8] = acc[mt][nt][3] * rs1;
        }
    }
    __syncthreads();

    const int b = row0 >> 12;
    const int n0 = row0 & (N_ - 1);
    float* base = zhat + (size_t)b * (C_ * N_) + n0;
#pragma unroll
    for (int p = 0; p < 32; ++p) {
        int e = p * NT_GEMM + tid;
        int cc = e >> 5, q4 = e & 31;
        float4 v = *(const float4*)(smf + (size_t)cc * 132 + q4 * 4);
        *(float4*)(base + (size_t)(c0 + cc) * N_ + q4 * 4) = v;
    }
}

// ---------------------------------------------------------------------------
extern "C" void kernel_launch(void* const* d_in, const int* in_sizes, int n_in,
                              void* d_out, int out_size) {
    const float* z   = (const float*)d_in[0];
    const float* mem = (const float*)d_in[1];
    float* zhat = (float*)d_out;
    float* attn = zhat + (size_t)B_ * C_ * N_;

    cudaFuncSetAttribute(k_zt_h, cudaFuncAttributeMaxDynamicSharedMemorySize, C_ * 33 * 4);
    cudaFuncSetAttribute(k_gemm1_h, cudaFuncAttributeMaxDynamicSharedMemorySize, DYN_SMEM);
    cudaFuncSetAttribute(k_gemm2_h, cudaFuncAttributeMaxDynamicSharedMemorySize, DYN_SMEM);

    k_rnorm_m<<<M_, 128>>>(mem);
    k_prep<<<dim3(C_ / 32, M_ / 32), dim3(32, 32)>>>(mem);
    k_zt_h<<<BN_ / 32, 256, C_ * 33 * 4>>>(z);
    k_gemm1_h<<<dim3(M_ / 128, BN_ / 128), NT_GEMM, DYN_SMEM>>>();
    k_finalize<<<BN_, 128>>>(attn);
    k_gemm2_h<<<dim3(C_ / 128, BN_ / 128), NT_GEMM, DYN_SMEM>>>(zhat);
}